// round 17
// baseline (speedup 1.0000x reference)
#include <cuda_runtime.h>
#include <cuda_fp16.h>
#include <cuda_bf16.h>
#include <stdint.h>

// ============================================================================
// AWQ 4-bit linear: out[128,8192] = x[128,8192] @ dequant(W)^T + bias
// mma.sync.m16n8k16. B never exists as fp16 in SMEM: packed int4 words are
// cp.async'd (4KB/chunk), broadcast-LDS'd, and dequantized IN REGISTERS into
// mma B-fragments — overlapped 1 step ahead of the consuming mma group, with
// A-fragments ldmatrix'd 2 steps ahead (3-buffer ring). This cuts the SMEM
// crossbar load per chunk from ~1400 to ~900 cyc AND hides LDSM/dequant
// latency under tensor work (r15 showed the math is exact; r16 showed 1-deep
// prefetch is insufficient under CTA-wide LDSM queue contention).
// x scratch is stored k-PERMUTED (pairs (t,t+4) per 8-group) to match the
// lop3 nibble order. zero/scale -> half2(1024+z, s) table.
// CTA: 256 thr, 8 warps, 4(M)x2(N), warp tile 32x32, N_TILE=64 -> 128 CTAs.
// 3-stage ring (A fp16 34KB + B packed 5KB), ONE barrier per chunk.
// ============================================================================

#define THREADS   256
#define N_TILE    64
#define K_DIM     8192
#define QW_COLS   1024
#define NCHUNK    64
#define A_ROW     272                 // 256B data + 16B pad
#define A_STAGE   (128 * A_ROW)       // 34816
#define B_ROW     80                  // 64B packed + 16B pad
#define B_STAGE   (64 * B_ROW)        // 5120
#define STAGE_SZ  (A_STAGE + B_STAGE) // 39936
#define NSTAGE    3
#define SMEM_TOTAL (NSTAGE * STAGE_SZ)  // 119808

#define X_ELEMS      1048576
#define SCALE_ELEMS  524288

__device__ __half   g_x[X_ELEMS];        // k-permuted: 8-group stored as (t, t+4) pairs
__device__ __half   g_scales[SCALE_ELEMS];
__device__ uint32_t g_zs[SCALE_ELEMS];   // half2(1024+z, s) per (n, group)
__device__ int      g_dtype;             // 0 fp32, 1 fp16, 2 bf16 storage

// ---------------------------------------------------------------------------
// dtype detection from scales (values in (0.001, 0.02))
// ---------------------------------------------------------------------------
__global__ void detect_dtype_kernel(const uint32_t* __restrict__ scales_raw) {
    const int lane = threadIdx.x;
    int cntHi = 0, cntLo = 0;
#pragma unroll
    for (int i = 0; i < 8; i++) {
        const uint32_t w = scales_raw[lane * 8 + i];
        const uint32_t eHi = (w >> 23) & 0xFF;
        const uint32_t eLo = (w >> 7) & 0xFF;
        cntHi += (eHi >= 110 && eHi <= 126);
        cntLo += (eLo >= 110 && eLo <= 126);
    }
#pragma unroll
    for (int off = 16; off > 0; off >>= 1) {
        cntHi += __shfl_xor_sync(0xFFFFFFFF, cntHi, off);
        cntLo += __shfl_xor_sync(0xFFFFFFFF, cntLo, off);
    }
    if (lane == 0) g_dtype = (cntHi > 192) ? ((cntLo > 192) ? 2 : 0) : 1;
}

// Plain conversion — used for scales.
__global__ void convert_kernel(const void* __restrict__ src, __half* __restrict__ dst, int n) {
    const int dt = g_dtype;
    const int stride = gridDim.x * blockDim.x;
    int i = blockIdx.x * blockDim.x + threadIdx.x;
    if (dt == 0) {
        const float4* s4 = (const float4*)src;
        for (; i < n / 4; i += stride) {
            const float4 v = s4[i];
            __half2 lo = __floats2half2_rn(v.x, v.y);
            __half2 hi = __floats2half2_rn(v.z, v.w);
            uint2 o;
            o.x = *reinterpret_cast<uint32_t*>(&lo);
            o.y = *reinterpret_cast<uint32_t*>(&hi);
            *reinterpret_cast<uint2*>(dst + i * 4) = o;
        }
    } else if (dt == 2) {
        const __nv_bfloat162* s2 = (const __nv_bfloat162*)src;
        for (; i < n / 4; i += stride) {
            const __nv_bfloat162 a = s2[i * 2], b = s2[i * 2 + 1];
            __half2 lo = __floats2half2_rn(__bfloat162float(a.x), __bfloat162float(a.y));
            __half2 hi = __floats2half2_rn(__bfloat162float(b.x), __bfloat162float(b.y));
            uint2 o;
            o.x = *reinterpret_cast<uint32_t*>(&lo);
            o.y = *reinterpret_cast<uint32_t*>(&hi);
            *reinterpret_cast<uint2*>(dst + i * 4) = o;
        }
    } else {
        const uint2* s2 = (const uint2*)src;
        for (; i < n / 4; i += stride)
            *reinterpret_cast<uint2*>(dst + i * 4) = s2[i];
    }
}

// x conversion WITH k-permutation: each 8-group stored as pairs (t, t+4).
__global__ void convert_x_kernel(const void* __restrict__ src, __half* __restrict__ dst) {
    const int dt = g_dtype;
    const int g = blockIdx.x * blockDim.x + threadIdx.x;   // 8-element group
    if (g >= X_ELEMS / 8) return;
    uint4 o;
    if (dt == 0) {
        const float4* s4 = (const float4*)src;
        const float4 a = s4[g * 2], b = s4[g * 2 + 1];     // f0..f3, f4..f7
        __half2 h0 = __floats2half2_rn(a.x, b.x);
        __half2 h1 = __floats2half2_rn(a.y, b.y);
        __half2 h2 = __floats2half2_rn(a.z, b.z);
        __half2 h3 = __floats2half2_rn(a.w, b.w);
        o.x = *reinterpret_cast<uint32_t*>(&h0);
        o.y = *reinterpret_cast<uint32_t*>(&h1);
        o.z = *reinterpret_cast<uint32_t*>(&h2);
        o.w = *reinterpret_cast<uint32_t*>(&h3);
    } else if (dt == 2) {
        const __nv_bfloat16* sb = (const __nv_bfloat16*)src + g * 8;
        float f[8];
#pragma unroll
        for (int t = 0; t < 8; t++) f[t] = __bfloat162float(sb[t]);
        __half2 h0 = __floats2half2_rn(f[0], f[4]);
        __half2 h1 = __floats2half2_rn(f[1], f[5]);
        __half2 h2 = __floats2half2_rn(f[2], f[6]);
        __half2 h3 = __floats2half2_rn(f[3], f[7]);
        o.x = *reinterpret_cast<uint32_t*>(&h0);
        o.y = *reinterpret_cast<uint32_t*>(&h1);
        o.z = *reinterpret_cast<uint32_t*>(&h2);
        o.w = *reinterpret_cast<uint32_t*>(&h3);
    } else {
        const uint4 v = reinterpret_cast<const uint4*>(src)[g];
        o.x = __byte_perm(v.x, v.z, 0x5410);
        o.y = __byte_perm(v.x, v.z, 0x7632);
        o.z = __byte_perm(v.y, v.w, 0x5410);
        o.w = __byte_perm(v.y, v.w, 0x7632);
    }
    reinterpret_cast<uint4*>(dst)[g] = o;
}

// Precompute half2(1024+z, s) per (n, group).
__global__ void build_zs_kernel(const int* __restrict__ qzeros) {
    const int idx = blockIdx.x * blockDim.x + threadIdx.x;
    if (idx >= SCALE_ELEMS) return;
    const int n = idx >> 6, g = idx & 63;
    const int z = (qzeros[n * 8 + (g >> 3)] >> ((g & 7) * 4)) & 15;
    const __half zp = __float2half_rn(1024.0f + (float)z);
    const __half s = g_scales[idx];
    const __half2 pack = __halves2half2(zp, s);
    g_zs[idx] = *reinterpret_cast<const uint32_t*>(&pack);
}

// ---------------------------------------------------------------------------
// GEMM helpers
// ---------------------------------------------------------------------------
static __device__ __forceinline__ uint32_t smem_u32(const void* p) {
    uint32_t r;
    asm("{ .reg .u64 t; cvta.to.shared.u64 t, %1; cvt.u32.u64 %0, t; }" : "=r"(r) : "l"(p));
    return r;
}
static __device__ __forceinline__ uint32_t h2u(__half2 h) {
    return *reinterpret_cast<uint32_t*>(&h);
}
static __device__ __forceinline__ void cp_async16(uint32_t dst, const void* src) {
    asm volatile("cp.async.cg.shared.global [%0], [%1], 16;" :: "r"(dst), "l"(src) : "memory");
}
static __device__ __forceinline__ void cp_commit() {
    asm volatile("cp.async.commit_group;" ::: "memory");
}
template <int N>
static __device__ __forceinline__ void cp_wait() {
    asm volatile("cp.async.wait_group %0;" :: "n"(N) : "memory");
}
static __device__ __forceinline__ void ldsm_x4(uint32_t* r, uint32_t addr) {
    asm volatile("ldmatrix.sync.aligned.m8n8.x4.shared.b16 {%0,%1,%2,%3}, [%4];"
                 : "=r"(r[0]), "=r"(r[1]), "=r"(r[2]), "=r"(r[3]) : "r"(addr));
}
static __device__ __forceinline__ uint4 lds128(uint32_t addr) {
    uint4 r;
    asm volatile("ld.shared.v4.u32 {%0,%1,%2,%3}, [%4];"
                 : "=r"(r.x), "=r"(r.y), "=r"(r.z), "=r"(r.w) : "r"(addr));
    return r;
}
static __device__ __forceinline__ void mma16816(float* d, const uint32_t* a, const uint32_t* b) {
    asm volatile("mma.sync.aligned.m16n8k16.row.col.f32.f16.f16.f32 "
                 "{%0,%1,%2,%3}, {%4,%5,%6,%7}, {%8,%9}, {%0,%1,%2,%3};"
                 : "+f"(d[0]), "+f"(d[1]), "+f"(d[2]), "+f"(d[3])
                 : "r"(a[0]), "r"(a[1]), "r"(a[2]), "r"(a[3]), "r"(b[0]), "r"(b[1]));
}
// One b-fragment register from a (pre-shifted) packed word: nibbles (t, t+4)
// -> half2, exact (v - (1024+z)) then single-rounded * s.
static __device__ __forceinline__ uint32_t dqreg(uint32_t v, __half2 zp2, __half2 s2) {
    uint32_t h;
    asm("lop3.b32 %0, %1, 0x000F000F, 0x64006400, 0xEA;" : "=r"(h) : "r"(v));
    return h2u(__hmul2(__hsub2(*reinterpret_cast<__half2*>(&h), zp2), s2));
}

extern __shared__ char dyn_smem[];

__global__ void __launch_bounds__(THREADS, 1)
awq_kernel(const int* __restrict__ qweight, const float* __restrict__ bias,
           float* __restrict__ out)
{
    const __half* x = g_x;
    const uint32_t sb = smem_u32(dyn_smem);
    const int tid = threadIdx.x;
    const int wid = tid >> 5;
    const int lid = tid & 31;
    const int n0 = blockIdx.x * N_TILE;

    // ---- A fill: 2048 16B-slots (128 rows x 16 units), 8 per thread ----
    uint32_t a_dst_off[8], a_src_off[8];
#pragma unroll
    for (int it = 0; it < 8; it++) {
        const int j = tid + THREADS * it;
        const int row = j >> 4, u = j & 15;
        a_dst_off[it] = (uint32_t)(row * A_ROW + u * 16);
        a_src_off[it] = (uint32_t)(row * K_DIM + u * 8);
    }
    // ---- B fill: 256 16B-slots (64 rows x 4 units), 1 per thread ----
    const uint32_t b_dst_off = (uint32_t)((tid >> 2) * B_ROW + (tid & 3) * 16);
    const int* b_src = qweight + (size_t)(n0 + (tid >> 2)) * QW_COLS + (tid & 3) * 4;

    // ---- compute-side: warp grid 4(M) x 2(N), warp tile 32x32 ----
    const int warp_m = wid >> 1;                 // 0..3
    const int warp_n = wid & 1;                  // 0..1
    uint32_t rowA_off[2];
#pragma unroll
    for (int mt = 0; mt < 2; mt++)
        rowA_off[mt] = (uint32_t)((warp_m * 32 + mt * 16 + (lid & 15)) * A_ROW
                                  + ((lid >> 4) & 1) * 16);
    const int sh = (lid & 3) * 4;                // nibble shift for this lane
    const int nrow_l = warp_n * 32 + (lid >> 2); // local B row (+ nt*8)
    uint32_t bOff[4];
    const uint32_t* zs_ptr[4];
#pragma unroll
    for (int nt = 0; nt < 4; nt++) {
        bOff[nt] = (uint32_t)((nrow_l + nt * 8) * B_ROW);
        zs_ptr[nt] = g_zs + (size_t)(n0 + nrow_l + nt * 8) * 64;
    }

    float acc[2][4][4];
#pragma unroll
    for (int mt = 0; mt < 2; mt++)
#pragma unroll
        for (int nt = 0; nt < 4; nt++)
#pragma unroll
            for (int e = 0; e < 4; e++) acc[mt][nt][e] = 0.0f;

    uint32_t zs_cur[4], zs_nxt[4];

    auto fill = [&](int i, int stage) {
        const uint32_t as = sb + stage * STAGE_SZ;
        const __half* xp = x + i * 128;
#pragma unroll
        for (int it = 0; it < 8; it++)
            cp_async16(as + a_dst_off[it], xp + a_src_off[it]);
        cp_async16(as + A_STAGE + b_dst_off, b_src + i * 16);
        cp_commit();
    };

    // ---- prologue ----
    fill(0, 0);
    fill(1, 1);
#pragma unroll
    for (int nt = 0; nt < 4; nt++) zs_cur[nt] = zs_ptr[nt][0];

    // ---- mainloop: ONE barrier per chunk; 2-deep A ring, 1-deep B dequant ----
#pragma unroll 1
    for (int i = 0; i < NCHUNK; i++) {
        if (i + 1 < NCHUNK) cp_wait<1>(); else cp_wait<0>();
        __syncthreads();                 // A(i)+B(i) visible; stage (i+2)%3 free

        const uint32_t ab = sb + (i % 3) * STAGE_SZ;
        const uint32_t bb = ab + A_STAGE;

        __half2 zp2[4], s2[4];
#pragma unroll
        for (int nt = 0; nt < 4; nt++) {
            const __half2 zs = *reinterpret_cast<const __half2*>(&zs_cur[nt]);
            zp2[nt] = __half2half2(__low2half(zs));
            s2[nt]  = __half2half2(__high2half(zs));
        }

        // Prime: packed-B quads p0,p1; A fragments for steps 0,1.
        uint4 wq[2][4];                  // slot ring: slot = p & 1
        uint32_t af[3][2][4];            // A ring: af[w % 3]
        uint32_t bf[2][4][2];            // B frag double buffer
#pragma unroll
        for (int nt = 0; nt < 4; nt++) wq[0][nt] = lds128(bb + bOff[nt]);
        ldsm_x4(af[0][0], ab + rowA_off[0]);
        ldsm_x4(af[0][1], ab + rowA_off[1]);
        ldsm_x4(af[1][0], ab + rowA_off[0] + 32);
        ldsm_x4(af[1][1], ab + rowA_off[1] + 32);
#pragma unroll
        for (int nt = 0; nt < 4; nt++) wq[1][nt] = lds128(bb + bOff[nt] + 16);

        // Overlap: staging for chunk i+2 + zs prefetch for i+1.
        if (i + 2 < NCHUNK) fill(i + 2, (i + 2) % 3);
        if (i + 1 < NCHUNK) {
#pragma unroll
            for (int nt = 0; nt < 4; nt++) zs_nxt[nt] = zs_ptr[nt][i + 1];
        }

        // Dequant step 0 fragments (p0, words .x/.y).
#pragma unroll
        for (int nt = 0; nt < 4; nt++) {
            bf[0][nt][0] = dqreg(wq[0][nt].x >> sh, zp2[nt], s2[nt]);
            bf[0][nt][1] = dqreg(wq[0][nt].y >> sh, zp2[nt], s2[nt]);
        }

#pragma unroll
        for (int w = 0; w < 8; w++) {
            const int cur = w & 1, nxt = cur ^ 1;
            // refill packed-B slots 2 steps ahead
            if (w == 1) {
#pragma unroll
                for (int nt = 0; nt < 4; nt++) wq[0][nt] = lds128(bb + bOff[nt] + 32);
            }
            if (w == 3) {
#pragma unroll
                for (int nt = 0; nt < 4; nt++) wq[1][nt] = lds128(bb + bOff[nt] + 48);
            }
            // A fragments 2 steps ahead
            if (w < 6) {
                ldsm_x4(af[(w + 2) % 3][0], ab + rowA_off[0] + 32 * (w + 2));
                ldsm_x4(af[(w + 2) % 3][1], ab + rowA_off[1] + 32 * (w + 2));
            }
            // dequant next step's B fragments (step w+1: p=(w+1)>>1, slot=p&1)
            if (w < 7) {
                const int s = w + 1, slot = (s >> 1) & 1, e = s & 1;
#pragma unroll
                for (int nt = 0; nt < 4; nt++) {
                    const uint32_t w0 = e ? wq[slot][nt].z : wq[slot][nt].x;
                    const uint32_t w1 = e ? wq[slot][nt].w : wq[slot][nt].y;
                    bf[nxt][nt][0] = dqreg(w0 >> sh, zp2[nt], s2[nt]);
                    bf[nxt][nt][1] = dqreg(w1 >> sh, zp2[nt], s2[nt]);
                }
            }
            // 8 mma of current step
#pragma unroll
            for (int mt = 0; mt < 2; mt++) {
                mma16816(acc[mt][0], af[w % 3][mt], bf[cur][0]);
                mma16816(acc[mt][1], af[w % 3][mt], bf[cur][1]);
                mma16816(acc[mt][2], af[w % 3][mt], bf[cur][2]);
                mma16816(acc[mt][3], af[w % 3][mt], bf[cur][3]);
            }
        }
#pragma unroll
        for (int nt = 0; nt < 4; nt++) zs_cur[nt] = zs_nxt[nt];
    }

    // ---- epilogue: fp16 round (match fp16 einsum), + fp32 bias ----
    const int r0 = lid >> 2;
    const int c0 = (lid & 3) * 2;
#pragma unroll
    for (int mt = 0; mt < 2; mt++) {
#pragma unroll
        for (int nt = 0; nt < 4; nt++) {
            const int n = n0 + warp_n * 32 + nt * 8 + c0;
            const float bx = bias[n], by = bias[n + 1];
            const int m = warp_m * 32 + mt * 16 + r0;
            float2 o0, o1;
            o0.x = __half2float(__float2half_rn(acc[mt][nt][0])) + bx;
            o0.y = __half2float(__float2half_rn(acc[mt][nt][1])) + by;
            o1.x = __half2float(__float2half_rn(acc[mt][nt][2])) + bx;
            o1.y = __half2float(__float2half_rn(acc[mt][nt][3])) + by;
            *reinterpret_cast<float2*>(out + (size_t)m * 8192 + n) = o0;
            *reinterpret_cast<float2*>(out + (size_t)(m + 8) * 8192 + n) = o1;
        }
    }
}

// ===========================================================================
// Host: bind inputs BY ELEMENT COUNT (all distinct) — immune to ordering.
//   x 1048576 | qweight 8388608 | scales 524288 | qzeros 65536 | bias 8192
// ===========================================================================
extern "C" void kernel_launch(void* const* d_in, const int* in_sizes, int n_in,
                              void* d_out, int out_size) {
    const void* x_raw = nullptr;
    const int* qweight = nullptr;
    const void* scales_raw = nullptr;
    const int* qzeros = nullptr;
    const float* bias = nullptr;

    for (int i = 0; i < n_in; i++) {
        switch (in_sizes[i]) {
            case X_ELEMS:     x_raw      = d_in[i];               break;
            case 8388608:     qweight    = (const int*)d_in[i];   break;
            case SCALE_ELEMS: scales_raw = d_in[i];               break;
            case 65536:       qzeros     = (const int*)d_in[i];   break;
            case 8192:        bias       = (const float*)d_in[i]; break;
            default: break;
        }
    }

    float* out = (float*)d_out;

    __half* gx = nullptr;
    __half* gs = nullptr;
    cudaGetSymbolAddress((void**)&gx, g_x);
    cudaGetSymbolAddress((void**)&gs, g_scales);

    detect_dtype_kernel<<<1, 32>>>((const uint32_t*)scales_raw);
    convert_x_kernel<<<(X_ELEMS / 8 + 255) / 256, 256>>>(x_raw, gx);
    convert_kernel<<<64, 256>>>(scales_raw, gs, SCALE_ELEMS);
    build_zs_kernel<<<SCALE_ELEMS / 256, 256>>>(qzeros);

    cudaFuncSetAttribute(awq_kernel, cudaFuncAttributeMaxDynamicSharedMemorySize, SMEM_TOTAL);
    awq_kernel<<<8192 / N_TILE, THREADS, SMEM_TOTAL>>>(qweight, bias, out);
}